// round 12
// baseline (speedup 1.0000x reference)
#include <cuda_runtime.h>
#include <cuda_fp16.h>
#include <stdint.h>
#include <math.h>

#define NP 100000
#define NA 50000
#define NEDGE 250000

#define XS2 72                         // X chunk stride (halves): 64 + 8 pad
#define WS2 72                         // W chunk stride (halves): 64 + 8 pad
#define XCH_HALVES (128*XS2)           // 9216
#define WCH_HALVES (64*WS2)            // 4608
#define STAGE_HALVES (XCH_HALVES + WCH_HALVES)   // 13824
#define SMEM_BYTES (2*STAGE_HALVES*2)  // 55296

// ---------------- scratch ----------------
__device__ __half g_xp[(size_t)NP*128];
__device__ __half g_xa[(size_t)NA*128];
__device__ __half g_actp[(size_t)NP*640];   // [q k1 v1 k2 v2]
__device__ __half g_acta[(size_t)NA*384];   // [q k0 v0]
__device__ __half g_aggp[(size_t)NP*128];   // gelu'd, fp16
__device__ __half g_agga[(size_t)NA*128];
__device__ __half g_wph[2][128*640];
__device__ float  g_bp[2][640];
__device__ __half g_wah[2][128*384];
__device__ float  g_ba[2][384];
__device__ __half g_wlinh[128*128];
__device__ __half g_awh[4][128*128];
__device__ int    g_deg[3*NP];
__device__ int    g_off[3*NP+1];
__device__ int    g_cur[3*NP];
__device__ int    g_srcs[3*NEDGE];
__device__ int    g_part[512];

__device__ __forceinline__ float gelu_f(float x){
    return 0.5f*x*(1.0f + erff(x*0.70710678118654752f));
}
__device__ __forceinline__ float4 h4f(uint2 u){
    __half2 a = *(__half2*)&u.x, b = *(__half2*)&u.y;
    float2 fa = __half22float2(a), fb = __half22float2(b);
    return make_float4(fa.x, fa.y, fb.x, fb.y);
}
__device__ __forceinline__ unsigned smem_u32(const void* p){
    unsigned r;
    asm("{ .reg .u64 t; cvta.to.shared.u64 t, %1; cvt.u32.u64 %0, t; }" : "=r"(r) : "l"(p));
    return r;
}
__device__ __forceinline__ void cp_async16(unsigned sa, const void* ga, int sz){
    asm volatile("cp.async.cg.shared.global [%0], [%1], 16, %2;" :: "r"(sa), "l"(ga), "r"(sz));
}
__device__ __forceinline__ void ldmA(unsigned a[4], unsigned addr){
    asm volatile("ldmatrix.sync.aligned.m8n8.x4.shared.b16 {%0,%1,%2,%3}, [%4];"
        : "=r"(a[0]),"=r"(a[1]),"=r"(a[2]),"=r"(a[3]) : "r"(addr));
}
__device__ __forceinline__ void ldmBT(unsigned b[4], unsigned addr){
    asm volatile("ldmatrix.sync.aligned.m8n8.x4.trans.shared.b16 {%0,%1,%2,%3}, [%4];"
        : "=r"(b[0]),"=r"(b[1]),"=r"(b[2]),"=r"(b[3]) : "r"(addr));
}
__device__ __forceinline__ void mma16816(float d[4], const unsigned a[4], const unsigned* b){
    asm volatile("mma.sync.aligned.m16n8k16.row.col.f32.f16.f16.f32 "
        "{%0,%1,%2,%3},{%4,%5,%6,%7},{%8,%9},{%0,%1,%2,%3};"
        : "+f"(d[0]),"+f"(d[1]),"+f"(d[2]),"+f"(d[3])
        : "r"(a[0]),"r"(a[1]),"r"(a[2]),"r"(a[3]),"r"(b[0]),"r"(b[1]));
}

// ---------------- fp16 mma GEMM: [N,128] x [128,Nw], 128x64 block tile, cp.async 2-stage ----------------
// 8 warps, each 16 rows x 64 cols => 32 accum floats/thread => 3 blocks/SM
// mode bit0: X is fp32 ; bit1: blend y=g*(acc+b)+(1-g)*Xold ; bit2: write out2 fp32 ; bit3: skip Y
__global__ void __launch_bounds__(256, 3)
gemm_mma(const void* __restrict__ Xv, const __half* __restrict__ W, int ldw,
         const float* __restrict__ B, __half* __restrict__ Y, int ldy,
         const __half* __restrict__ Xold, const float* __restrict__ skipPtr,
         float* __restrict__ out2, int out2N,
         int N, int mode)
{
    extern __shared__ __half sh[];
    const int tid = threadIdx.x, warp = tid>>5, lane = tid&31;
    const int bRow = blockIdx.x*128, colBase = blockIdx.y*64;

    __half* Xc[2] = { sh, sh + STAGE_HALVES };
    __half* Wcb[2] = { sh + XCH_HALVES, sh + STAGE_HALVES + XCH_HALVES };

    const bool async_path = !(mode & 1);

    if (async_path){
        const __half* Xh = (const __half*)Xv;
        #pragma unroll
        for (int c = 0; c < 2; c++){
            #pragma unroll
            for (int i = 0; i < 4; i++){
                int idx = tid + i*256;          // 1024 ops: 128 rows x 8 chunks
                int r = idx>>3, ch = idx&7;
                int gr = bRow + r;
                unsigned sa = smem_u32(Xc[c] + r*XS2 + ch*8);
                const void* ga = Xh + (size_t)gr*128 + c*64 + ch*8;
                cp_async16(sa, ga, (gr < N) ? 16 : 0);
            }
            #pragma unroll
            for (int i = 0; i < 2; i++){
                int idx = tid + i*256;          // 512 ops: 64 rows x 8 chunks
                int r = idx>>3, ch = idx&7;
                unsigned sa = smem_u32(Wcb[c] + r*WS2 + ch*8);
                const void* ga = W + (size_t)(c*64 + r)*ldw + colBase + ch*8;
                cp_async16(sa, ga, 16);
            }
            asm volatile("cp.async.commit_group;");
        }
    } else {
        const float* Xf = (const float*)Xv;
        #pragma unroll
        for (int c = 0; c < 2; c++){
            #pragma unroll
            for (int i = 0; i < 8; i++){
                int idx = tid + i*256;          // 2048 float4: 128 rows x 16
                int r = idx>>4, c4 = idx&15;
                int gr = bRow + r;
                float4 v = (gr < N) ? ((const float4*)Xf)[(size_t)gr*32 + c*16 + c4]
                                    : make_float4(0.f,0.f,0.f,0.f);
                __half2 h0 = __floats2half2_rn(v.x,v.y), h1 = __floats2half2_rn(v.z,v.w);
                uint2 u; u.x = *(unsigned*)&h0; u.y = *(unsigned*)&h1;
                *(uint2*)(Xc[c] + r*XS2 + c4*4) = u;
            }
            #pragma unroll
            for (int i = 0; i < 2; i++){
                int idx = tid + i*256;
                int r = idx>>3, ch = idx&7;
                uint4 v = *(const uint4*)(W + (size_t)(c*64 + r)*ldw + colBase + ch*8);
                *(uint4*)(Wcb[c] + r*WS2 + ch*8) = v;
            }
        }
        __syncthreads();
    }

    float d[8][4];
    #pragma unroll
    for (int ni=0;ni<8;ni++)
        #pragma unroll
        for (int k=0;k<4;k++) d[ni][k]=0.f;

    #pragma unroll
    for (int c = 0; c < 2; c++){
        if (async_path){
            if (c == 0) asm volatile("cp.async.wait_group 1;");
            else        asm volatile("cp.async.wait_group 0;");
            __syncthreads();
        }
        unsigned xA = smem_u32(Xc[c]) + (unsigned)(((warp*16 + (lane&15))*XS2 + (lane>>4)*8)*2);
        unsigned wB = smem_u32(Wcb[c]) + (unsigned)((((lane&15))*WS2 + (lane>>4)*8)*2);
        #pragma unroll
        for (int ks = 0; ks < 4; ks++){
            unsigned a0[4];
            ldmA(a0, xA + ks*32);
            #pragma unroll
            for (int nt = 0; nt < 4; nt++){
                unsigned bb[4];
                ldmBT(bb, wB + (unsigned)(ks*16*WS2*2) + nt*32);
                mma16816(d[2*nt],   a0, bb);
                mma16816(d[2*nt+1], a0, bb+2);
            }
        }
    }

    float gate = 1.f, og = 0.f;
    if (mode & 2){ gate = 1.f/(1.f + expf(-skipPtr[0])); og = 1.f - gate; }
    const int g = lane>>2, t2 = (lane&3)*2;
    float2 bv[8];
    #pragma unroll
    for (int ni=0;ni<8;ni++) bv[ni] = *(const float2*)(B + colBase + ni*8 + t2);

    int rbase = bRow + warp*16 + g;
    #pragma unroll
    for (int ni=0;ni<8;ni++){
        int c = colBase + ni*8 + t2;
        #pragma unroll
        for (int h=0; h<2; h++){
            int r = rbase + h*8;
            if (r >= N) continue;
            float rx = d[ni][2*h]   + bv[ni].x;
            float ry = d[ni][2*h+1] + bv[ni].y;
            if (mode & 2){
                __half2 xo = *(const __half2*)(Xold + (size_t)r*128 + c);
                float2 xf = __half22float2(xo);
                rx = gate*rx + og*xf.x;
                ry = gate*ry + og*xf.y;
            }
            if (!(mode & 8)){
                __half2 hh = __floats2half2_rn(rx, ry);
                *(__half2*)(Y + (size_t)r*ldy + c) = hh;
            }
            if ((mode & 4) && r < out2N)
                *(float2*)(out2 + (size_t)r*128 + c) = make_float2(rx, ry);
        }
    }
}

// ---------------- weight prep: fold relation transforms, emit fp16 ----------------
__global__ void prep_weights(const float* __restrict__ k_w, const float* __restrict__ k_b,
                             const float* __restrict__ v_w, const float* __restrict__ v_b,
                             const float* __restrict__ q_w, const float* __restrict__ q_b,
                             const float* __restrict__ a_rel, const float* __restrict__ m_rel,
                             const float* __restrict__ lin_w, const float* __restrict__ a_w)
{
    int fid = blockIdx.x;           // 0..20
    int jc = threadIdx.x;
    int i0 = blockIdx.y * 32;

    if (fid >= 16){
        const float* W = (fid == 16) ? lin_w : a_w + (size_t)(fid-17)*16384;
        __half* D = (fid == 16) ? g_wlinh : g_awh[fid-17];
        for (int i = i0; i < i0+32; i++) D[i*128 + jc] = __float2half(W[i*128 + jc]);
        return;
    }

    int l = fid >> 3, sid = fid & 7;
    bool paper = sid < 5;
    __half* dstW; float* dstB; int stride, col;
    if (paper){ dstW = g_wph[l]; dstB = g_bp[l]; stride = 640; col = sid*128; }
    else      { dstW = g_wah[l]; dstB = g_ba[l]; stride = 384; col = (sid-5)*128; }

    const float *W, *Bi, *R = nullptr;
    switch (sid){
        case 0: W = q_w + (size_t)(l*2+0)*16384; Bi = q_b + (l*2+0)*128; break;
        case 1: W = k_w + (size_t)(l*2+0)*16384; Bi = k_b + (l*2+0)*128; R = a_rel + (size_t)(l*3+1)*4096; break;
        case 2: W = v_w + (size_t)(l*2+0)*16384; Bi = v_b + (l*2+0)*128; R = m_rel + (size_t)(l*3+1)*4096; break;
        case 3: W = k_w + (size_t)(l*2+0)*16384; Bi = k_b + (l*2+0)*128; R = a_rel + (size_t)(l*3+2)*4096; break;
        case 4: W = v_w + (size_t)(l*2+0)*16384; Bi = v_b + (l*2+0)*128; R = m_rel + (size_t)(l*3+2)*4096; break;
        case 5: W = q_w + (size_t)(l*2+1)*16384; Bi = q_b + (l*2+1)*128; break;
        case 6: W = k_w + (size_t)(l*2+1)*16384; Bi = k_b + (l*2+1)*128; R = a_rel + (size_t)(l*3+0)*4096; break;
        default:W = v_w + (size_t)(l*2+1)*16384; Bi = v_b + (l*2+1)*128; R = m_rel + (size_t)(l*3+0)*4096; break;
    }

    if (R == nullptr){
        for (int i = i0; i < i0+32; i++) dstW[i*stride + col + jc] = __float2half(W[i*128 + jc]);
        if (blockIdx.y == 0) dstB[col + jc] = Bi[jc];
        return;
    }
    __shared__ float Rs[4096];
    for (int i = threadIdx.x; i < 4096; i += 128) Rs[i] = R[i];
    __syncthreads();
    int h = jc >> 5, j = jc & 31;
    const float* Rh = Rs + h*1024 + j;
    for (int i = i0; i < i0+32; i++){
        float acc = 0.f;
        #pragma unroll
        for (int dd = 0; dd < 32; dd++) acc += W[i*128 + h*32 + dd] * Rh[dd*32];
        dstW[i*stride + col + jc] = __float2half(acc);
    }
    if (blockIdx.y == 0){
        float accb = 0.f;
        #pragma unroll
        for (int dd = 0; dd < 32; dd++) accb += Bi[h*32 + dd] * Rh[dd*32];
        dstB[col + jc] = accb;
    }
}

// ---------------- merged CSR build ----------------
__global__ void zero_int_kernel(int* __restrict__ p, int n){
    int i = blockIdx.x*blockDim.x + threadIdx.x;
    if (i < n) p[i] = 0;
}
__global__ void hist3_kernel(const int* __restrict__ d0, const int* __restrict__ d1,
                             const int* __restrict__ d2, int* __restrict__ deg){
    int i = blockIdx.x*blockDim.x + threadIdx.x;
    if (i >= 3*NEDGE) return;
    int t = i / NEDGE, e = i - t*NEDGE;
    int d = (t == 0) ? d0[e] : (t == 1) ? d1[e] : d2[e];
    atomicAdd(&deg[t*NP + d], 1);
}
__global__ void partial_kernel(const int* __restrict__ deg, int* __restrict__ part, int n){
    __shared__ int s[256];
    int tid = threadIdx.x;
    int base = blockIdx.x*1024 + tid*4;
    int sum = 0;
    #pragma unroll
    for (int j = 0; j < 4; j++) if (base + j < n) sum += deg[base + j];
    s[tid] = sum; __syncthreads();
    for (int d = 128; d > 0; d >>= 1){
        if (tid < d) s[tid] += s[tid + d];
        __syncthreads();
    }
    if (tid == 0) part[blockIdx.x] = s[0];
}
__global__ void scan_part_kernel(int* __restrict__ part, int nb){
    __shared__ int s[512];
    int tid = threadIdx.x;
    int v = (tid < nb) ? part[tid] : 0;
    s[tid] = v; __syncthreads();
    for (int d = 1; d < 512; d <<= 1){
        int t = (tid >= d) ? s[tid - d] : 0;
        __syncthreads();
        s[tid] += t;
        __syncthreads();
    }
    if (tid < nb) part[tid] = s[tid] - v;
}
__global__ void offsets_kernel(const int* __restrict__ deg, const int* __restrict__ part,
                               int* __restrict__ off, int* __restrict__ cur, int n, int E){
    __shared__ int s[256];
    int tid = threadIdx.x;
    int base = blockIdx.x*1024 + tid*4;
    int v[4];
    #pragma unroll
    for (int j = 0; j < 4; j++) v[j] = (base + j < n) ? deg[base + j] : 0;
    int tsum = v[0]+v[1]+v[2]+v[3];
    s[tid] = tsum; __syncthreads();
    for (int d = 1; d < 256; d <<= 1){
        int t = (tid >= d) ? s[tid - d] : 0;
        __syncthreads();
        s[tid] += t;
        __syncthreads();
    }
    int run = s[tid] - tsum + part[blockIdx.x];
    #pragma unroll
    for (int j = 0; j < 4; j++){
        if (base + j < n){ off[base + j] = run; cur[base + j] = run; }
        run += v[j];
    }
    if (blockIdx.x == 0 && tid == 0) off[n] = E;
}
__global__ void scatter3_kernel(const int* __restrict__ d0, const int* __restrict__ d1,
                                const int* __restrict__ d2, const int* __restrict__ s0,
                                const int* __restrict__ s1, const int* __restrict__ s2,
                                int* __restrict__ cur, int* __restrict__ srcs){
    int i = blockIdx.x*blockDim.x + threadIdx.x;
    if (i >= 3*NEDGE) return;
    int t = i / NEDGE, e = i - t*NEDGE;
    int d  = (t == 0) ? d0[e] : (t == 1) ? d1[e] : d2[e];
    int sv = (t == 0) ? s0[e] : (t == 1) ? s1[e] : s2[e];
    int pos = atomicAdd(&cur[t*NP + d], 1);
    srcs[pos] = sv;
}

// ---------------- single-pass fused attention aggregation (4-wide MLP) ----------------
__device__ __forceinline__ float4 agg_one(int e0, int e1, const int* __restrict__ srcs,
                                          const uint2* __restrict__ buf, int stride4,
                                          int kOff4, int vOff4, float ph, float4 q4, int lane)
{
    float den = 0.f;
    float4 acc = make_float4(0.f,0.f,0.f,0.f);
    for (int base = e0; base < e1; base += 32){
        int m = min(32, e1 - base);
        int myS = (base + lane < e1) ? srcs[base + lane] : 0;
        int j = 0;
        for (; j + 4 <= m; j += 4){
            int s0 = __shfl_sync(0xffffffffu, myS, j);
            int s1 = __shfl_sync(0xffffffffu, myS, j+1);
            int s2 = __shfl_sync(0xffffffffu, myS, j+2);
            int s3 = __shfl_sync(0xffffffffu, myS, j+3);
            const uint2* r0 = buf + (size_t)s0*stride4;
            const uint2* r1 = buf + (size_t)s1*stride4;
            const uint2* r2 = buf + (size_t)s2*stride4;
            const uint2* r3 = buf + (size_t)s3*stride4;
            uint2 k0u = r0[kOff4 + lane], v0u = r0[vOff4 + lane];
            uint2 k1u = r1[kOff4 + lane], v1u = r1[vOff4 + lane];
            uint2 k2u = r2[kOff4 + lane], v2u = r2[vOff4 + lane];
            uint2 k3u = r3[kOff4 + lane], v3u = r3[vOff4 + lane];
            float4 k0 = h4f(k0u), k1 = h4f(k1u), k2 = h4f(k2u), k3 = h4f(k3u);
            float p0 = q4.x*k0.x + q4.y*k0.y + q4.z*k0.z + q4.w*k0.w;
            float p1 = q4.x*k1.x + q4.y*k1.y + q4.z*k1.z + q4.w*k1.w;
            float p2 = q4.x*k2.x + q4.y*k2.y + q4.z*k2.z + q4.w*k2.w;
            float p3 = q4.x*k3.x + q4.y*k3.y + q4.z*k3.z + q4.w*k3.w;
            p0 += __shfl_xor_sync(0xffffffffu, p0, 1);
            p1 += __shfl_xor_sync(0xffffffffu, p1, 1);
            p2 += __shfl_xor_sync(0xffffffffu, p2, 1);
            p3 += __shfl_xor_sync(0xffffffffu, p3, 1);
            p0 += __shfl_xor_sync(0xffffffffu, p0, 2);
            p1 += __shfl_xor_sync(0xffffffffu, p1, 2);
            p2 += __shfl_xor_sync(0xffffffffu, p2, 2);
            p3 += __shfl_xor_sync(0xffffffffu, p3, 2);
            p0 += __shfl_xor_sync(0xffffffffu, p0, 4);
            p1 += __shfl_xor_sync(0xffffffffu, p1, 4);
            p2 += __shfl_xor_sync(0xffffffffu, p2, 4);
            p3 += __shfl_xor_sync(0xffffffffu, p3, 4);
            float e0f = __expf(p0 * ph), e1f = __expf(p1 * ph);
            float e2f = __expf(p2 * ph), e3f = __expf(p3 * ph);
            den += (e0f + e1f) + (e2f + e3f);
            float4 v0 = h4f(v0u), v1 = h4f(v1u), v2 = h4f(v2u), v3 = h4f(v3u);
            acc.x += e0f*v0.x + e1f*v1.x + e2f*v2.x + e3f*v3.x;
            acc.y += e0f*v0.y + e1f*v1.y + e2f*v2.y + e3f*v3.y;
            acc.z += e0f*v0.z + e1f*v1.z + e2f*v2.z + e3f*v3.z;
            acc.w += e0f*v0.w + e1f*v1.w + e2f*v2.w + e3f*v3.w;
        }
        for (; j < m; j++){
            int s = __shfl_sync(0xffffffffu, myS, j);
            const uint2* row = buf + (size_t)s*stride4;
            float4 k4 = h4f(row[kOff4 + lane]);
            float4 v4 = h4f(row[vOff4 + lane]);
            float p = q4.x*k4.x + q4.y*k4.y + q4.z*k4.z + q4.w*k4.w;
            p += __shfl_xor_sync(0xffffffffu, p, 1);
            p += __shfl_xor_sync(0xffffffffu, p, 2);
            p += __shfl_xor_sync(0xffffffffu, p, 4);
            float ex = __expf(p * ph);
            den += ex;
            acc.x += ex*v4.x; acc.y += ex*v4.y;
            acc.z += ex*v4.z; acc.w += ex*v4.w;
        }
    }
    float inv = 1.f/(den + 1e-16f);
    acc.x *= inv; acc.y *= inv; acc.z *= inv; acc.w *= inv;
    return acc;
}

__device__ __forceinline__ void store_h4(__half* dst, float4 v){
    __half2 h0 = __floats2half2_rn(v.x, v.y);
    __half2 h1 = __floats2half2_rn(v.z, v.w);
    uint2 u; u.x = *(unsigned*)&h0; u.y = *(unsigned*)&h1;
    *(uint2*)dst = u;
}

__global__ void aggregate_all(const int* __restrict__ off, const int* __restrict__ srcs,
                              const uint2* __restrict__ actp, const uint2* __restrict__ acta,
                              const float* __restrict__ prel,
                              __half* __restrict__ aggp, __half* __restrict__ agga)
{
    int d = blockIdx.x*8 + (threadIdx.x >> 5);
    int lane = threadIdx.x & 31;
    int h = lane >> 3;
    if (d < NP){
        float4 q4 = h4f(actp[(size_t)d*160 + lane]);
        float ph0 = prel[0*4 + h] * 0.17677669529663687f;
        float ph2 = prel[2*4 + h] * 0.17677669529663687f;
        float4 res = agg_one(off[d], off[d+1], srcs, acta, 96, 32, 64, ph0, q4, lane);
        float4 r2  = agg_one(off[2*NP+d], off[2*NP+d+1], srcs, actp, 160, 96, 128, ph2, q4, lane);
        res.x = gelu_f(0.5f*(res.x + r2.x));
        res.y = gelu_f(0.5f*(res.y + r2.y));
        res.z = gelu_f(0.5f*(res.z + r2.z));
        res.w = gelu_f(0.5f*(res.w + r2.w));
        store_h4(aggp + (size_t)d*128 + lane*4, res);
    } else if (d < NP + NA){
        int da = d - NP;
        float4 q4 = h4f(acta[(size_t)da*96 + lane]);
        float ph1 = prel[1*4 + h] * 0.17677669529663687f;
        float4 res = agg_one(off[NP+da], off[NP+da+1], srcs, actp, 160, 32, 64, ph1, q4, lane);
        res.x = gelu_f(res.x); res.y = gelu_f(res.y);
        res.z = gelu_f(res.z); res.w = gelu_f(res.w);
        store_h4(agga + (size_t)da*128 + lane*4, res);
    }
}

// ---------------- misc ----------------
__global__ void gather_embed_kernel(const float* __restrict__ tab, const int* __restrict__ idx,
                                    __half* __restrict__ out, int n){
    int i = blockIdx.x*blockDim.x + threadIdx.x;
    if (i >= n*32) return;
    int node = i >> 5, c = i & 31;
    int src = idx[node];
    float4 v = ((const float4*)tab)[(size_t)src*32 + c];
    store_h4(out + (size_t)node*128 + c*4, v);
}

// ---------------- launch ----------------
extern "C" void kernel_launch(void* const* d_in, const int* in_sizes, int n_in,
                              void* d_out, int out_size)
{
    const float* x_paper     = (const float*)d_in[0];
    const int*   author_idx  = (const int*)  d_in[1];
    const float* embed_table = (const float*)d_in[2];
    const float* lin_w       = (const float*)d_in[3];
    const float* lin_b       = (const float*)d_in[4];
    const float* k_w         = (const float*)d_in[5];
    const float* k_b         = (const float*)d_in[6];
    const float* q_w         = (const float*)d_in[7];
    const float* q_b         = (const float*)d_in[8];
    const float* v_w         = (const float*)d_in[9];
    const float* v_b         = (const float*)d_in[10];
    const float* a_rel       = (const float*)d_in[11];
    const float* m_rel       = (const float*)d_in[12];
    const float* p_rel       = (const float*)d_in[13];
    const float* skip        = (const float*)d_in[14];
    const float* a_w         = (const float*)d_in[15];
    const float* a_b         = (const float*)d_in[16];
    const int*   w_src       = (const int*)  d_in[17];
    const int*   w_dst       = (const int*)  d_in[18];
    const int*   r_src       = (const int*)  d_in[19];
    const int*   r_dst       = (const int*)  d_in[20];
    const int*   c_src       = (const int*)  d_in[21];
    const int*   c_dst       = (const int*)  d_in[22];
    float* out = (float*)d_out;

    __half *xp,*xa,*actp,*acta,*aggp,*agga,*wlinh;
    __half *wph0,*wah0,*awh0;
    float *bp0,*ba0;
    int *deg,*off,*cur,*srcs,*part;
    cudaGetSymbolAddress((void**)&xp,   g_xp);
    cudaGetSymbolAddress((void**)&xa,   g_xa);
    cudaGetSymbolAddress((void**)&actp, g_actp);
    cudaGetSymbolAddress((void**)&acta, g_acta);
    cudaGetSymbolAddress((void**)&aggp, g_aggp);
    cudaGetSymbolAddress((void**)&agga, g_agga);
    cudaGetSymbolAddress((void**)&wlinh,g_wlinh);
    cudaGetSymbolAddress((void**)&wph0, g_wph);
    cudaGetSymbolAddress((void**)&wah0, g_wah);
    cudaGetSymbolAddress((void**)&awh0, g_awh);
    cudaGetSymbolAddress((void**)&bp0,  g_bp);
    cudaGetSymbolAddress((void**)&ba0,  g_ba);
    cudaGetSymbolAddress((void**)&deg,  g_deg);
    cudaGetSymbolAddress((void**)&off,  g_off);
    cudaGetSymbolAddress((void**)&cur,  g_cur);
    cudaGetSymbolAddress((void**)&srcs, g_srcs);
    cudaGetSymbolAddress((void**)&part, g_part);

    cudaFuncSetAttribute(gemm_mma, cudaFuncAttributeMaxDynamicSharedMemorySize, SMEM_BYTES);

    const int SMB = SMEM_BYTES;
    const int GP = (NP+127)/128, GA = (NA+127)/128;

    prep_weights<<<dim3(21,4),128>>>(k_w, k_b, v_w, v_b, q_w, q_b, a_rel, m_rel, lin_w, a_w);
    gather_embed_kernel<<<(NA*32+255)/256,256>>>(embed_table, author_idx, xa, NA);
    // input projection: X fp32 -> xp fp16 (sync path), 2 col tiles
    gemm_mma<<<dim3(GP,2),256,SMB>>>(x_paper, wlinh, 128, lin_b, xp, 128,
                                     nullptr, nullptr, nullptr, 0, NP, 1);

    for (int l = 0; l < 2; l++){
        gemm_mma<<<dim3(GP,10),256,SMB>>>(xp, wph0 + (size_t)l*128*640, 640, bp0 + l*640,
                                          actp, 640, nullptr, nullptr, nullptr, 0, NP, 0);
        gemm_mma<<<dim3(GA,6),256,SMB>>>(xa, wah0 + (size_t)l*128*384, 384, ba0 + l*384,
                                         acta, 384, nullptr, nullptr, nullptr, 0, NA, 0);

        if (l == 0){
            int n = 3*NP;
            int nb = (n + 1023)/1024;
            zero_int_kernel<<<(n+255)/256,256>>>(deg, n);
            hist3_kernel<<<(3*NEDGE+255)/256,256>>>(w_dst, r_dst, c_dst, deg);
            partial_kernel<<<nb,256>>>(deg, part, n);
            scan_part_kernel<<<1,512>>>(part, nb);
            offsets_kernel<<<nb,256>>>(deg, part, off, cur, n, 3*NEDGE);
            scatter3_kernel<<<(3*NEDGE+255)/256,256>>>(w_dst, r_dst, c_dst, w_src, r_src, c_src, cur, srcs);
        }

        aggregate_all<<<(NP+NA+7)/8,256>>>(off, srcs, (const uint2*)actp, (const uint2*)acta,
                                           p_rel + l*12, aggp, agga);

        // update: y = sigmoid(skip)*(acc + b) + (1-sigmoid(skip))*x   (gelu pre-applied in aggregate)
        int mode = (l == 1) ? (2|4|8) : 2;
        gemm_mma<<<dim3(GP,2),256,SMB>>>(aggp, awh0 + (size_t)(l*2+0)*16384, 128, a_b + (l*2+0)*128,
                                         xp, 128, xp, skip + l*2+0,
                                         out, (l==1)?50000:0, NP, mode);
        gemm_mma<<<dim3(GA,2),256,SMB>>>(agga, awh0 + (size_t)(l*2+1)*16384, 128, a_b + (l*2+1)*128,
                                         xa, 128, xa, skip + l*2+1,
                                         out + (size_t)50000*128, (l==1)?25000:0, NA, mode);
    }
}

// round 14
// speedup vs baseline: 1.1513x; 1.1513x over previous
#include <cuda_runtime.h>
#include <cuda_fp16.h>
#include <stdint.h>
#include <math.h>

#define NP 100000
#define NA 50000
#define NEDGE 250000

#define XS2 72                         // X chunk stride (halves): 64 + 8 pad
#define WS2 136                        // W chunk stride (halves): 128 + 8 pad
#define XCH_HALVES (128*XS2)           // 9216
#define WCH_HALVES (64*WS2)            // 8704
#define STAGE_HALVES (XCH_HALVES + WCH_HALVES)   // 17920
#define SMEM_BYTES (2*STAGE_HALVES*2)  // 71680

// ---------------- scratch ----------------
__device__ __half g_xp[(size_t)NP*128];
__device__ __half g_xa[(size_t)NA*128];
__device__ __half g_actp[(size_t)NP*640];   // [q k1 v1 k2 v2]
__device__ __half g_acta[(size_t)NA*384];   // [q k0 v0]
__device__ __half g_aggp[(size_t)NP*128];   // gelu'd, fp16
__device__ __half g_agga[(size_t)NA*128];
__device__ __half g_wph[2][128*640];
__device__ float  g_bp[2][640];
__device__ __half g_wah[2][128*384];
__device__ float  g_ba[2][384];
__device__ __half g_wlinh[128*128];
__device__ __half g_awh[4][128*128];
__device__ int    g_deg[3*NP];
__device__ int    g_off[3*NP+1];
__device__ int    g_cur[3*NP];
__device__ int    g_srcs[3*NEDGE];
__device__ int    g_part[512];

__device__ __forceinline__ float gelu_f(float x){
    return 0.5f*x*(1.0f + erff(x*0.70710678118654752f));
}
__device__ __forceinline__ float4 h4f(uint2 u){
    __half2 a = *(__half2*)&u.x, b = *(__half2*)&u.y;
    float2 fa = __half22float2(a), fb = __half22float2(b);
    return make_float4(fa.x, fa.y, fb.x, fb.y);
}
__device__ __forceinline__ unsigned smem_u32(const void* p){
    unsigned r;
    asm("{ .reg .u64 t; cvta.to.shared.u64 t, %1; cvt.u32.u64 %0, t; }" : "=r"(r) : "l"(p));
    return r;
}
__device__ __forceinline__ void cp_async16(unsigned sa, const void* ga, int sz){
    asm volatile("cp.async.cg.shared.global [%0], [%1], 16, %2;" :: "r"(sa), "l"(ga), "r"(sz));
}
__device__ __forceinline__ void ldmA(unsigned a[4], unsigned addr){
    asm volatile("ldmatrix.sync.aligned.m8n8.x4.shared.b16 {%0,%1,%2,%3}, [%4];"
        : "=r"(a[0]),"=r"(a[1]),"=r"(a[2]),"=r"(a[3]) : "r"(addr));
}
__device__ __forceinline__ void ldmBT(unsigned b[4], unsigned addr){
    asm volatile("ldmatrix.sync.aligned.m8n8.x4.trans.shared.b16 {%0,%1,%2,%3}, [%4];"
        : "=r"(b[0]),"=r"(b[1]),"=r"(b[2]),"=r"(b[3]) : "r"(addr));
}
__device__ __forceinline__ void mma16816(float d[4], const unsigned a[4], const unsigned* b){
    asm volatile("mma.sync.aligned.m16n8k16.row.col.f32.f16.f16.f32 "
        "{%0,%1,%2,%3},{%4,%5,%6,%7},{%8,%9},{%0,%1,%2,%3};"
        : "+f"(d[0]),"+f"(d[1]),"+f"(d[2]),"+f"(d[3])
        : "r"(a[0]),"r"(a[1]),"r"(a[2]),"r"(a[3]),"r"(b[0]),"r"(b[1]));
}

// ---------------- fp16 mma GEMM: [N,128] x [128,Nw], 128x128 tile, cp.async 2-stage ----------------
// mode bit0: X is fp32 ; bit1: blend y=g*(acc+b)+(1-g)*Xold ; bit2: write out2 fp32 ; bit3: skip Y
__global__ void __launch_bounds__(256, 2)
gemm_mma(const void* __restrict__ Xv, const __half* __restrict__ W, int ldw,
         const float* __restrict__ B, __half* __restrict__ Y, int ldy,
         const __half* __restrict__ Xold, const float* __restrict__ skipPtr,
         float* __restrict__ out2, int out2N,
         int N, int mode)
{
    extern __shared__ __half sh[];
    const int tid = threadIdx.x, warp = tid>>5, lane = tid&31;
    const int wr = warp>>1, wc = warp&1;
    const int bRow = blockIdx.x*128, colBase = blockIdx.y*128;

    __half* Xc[2] = { sh, sh + STAGE_HALVES };
    __half* Wcb[2] = { sh + XCH_HALVES, sh + STAGE_HALVES + XCH_HALVES };

    const bool async_path = !(mode & 1);

    if (async_path){
        const __half* Xh = (const __half*)Xv;
        #pragma unroll
        for (int c = 0; c < 2; c++){
            #pragma unroll
            for (int i = 0; i < 4; i++){
                int idx = tid + i*256;          // 1024 16B ops: 128 rows x 8
                int r = idx>>3, ch = idx&7;
                int gr = bRow + r;
                unsigned sa = smem_u32(Xc[c] + r*XS2 + ch*8);
                const void* ga = Xh + (size_t)gr*128 + c*64 + ch*8;
                cp_async16(sa, ga, (gr < N) ? 16 : 0);
            }
            #pragma unroll
            for (int i = 0; i < 4; i++){
                int idx = tid + i*256;          // 1024 16B ops: 64 rows x 16
                int r = idx>>4, ch = idx&15;
                unsigned sa = smem_u32(Wcb[c] + r*WS2 + ch*8);
                const void* ga = W + (size_t)(c*64 + r)*ldw + colBase + ch*8;
                cp_async16(sa, ga, 16);
            }
            asm volatile("cp.async.commit_group;");
        }
    } else {
        const float* Xf = (const float*)Xv;
        #pragma unroll
        for (int c = 0; c < 2; c++){
            #pragma unroll
            for (int i = 0; i < 8; i++){
                int idx = tid + i*256;          // 2048 float4: 128 rows x 16
                int r = idx>>4, c4 = idx&15;
                int gr = bRow + r;
                float4 v = (gr < N) ? ((const float4*)Xf)[(size_t)gr*32 + c*16 + c4]
                                    : make_float4(0.f,0.f,0.f,0.f);
                __half2 h0 = __floats2half2_rn(v.x,v.y), h1 = __floats2half2_rn(v.z,v.w);
                uint2 u; u.x = *(unsigned*)&h0; u.y = *(unsigned*)&h1;
                *(uint2*)(Xc[c] + r*XS2 + c4*4) = u;
            }
            #pragma unroll
            for (int i = 0; i < 4; i++){
                int idx = tid + i*256;
                int r = idx>>4, ch = idx&15;
                uint4 v = *(const uint4*)(W + (size_t)(c*64 + r)*ldw + colBase + ch*8);
                *(uint4*)(Wcb[c] + r*WS2 + ch*8) = v;
            }
        }
        __syncthreads();
    }

    float d[2][8][4];
    #pragma unroll
    for (int mi=0;mi<2;mi++)
        #pragma unroll
        for (int ni=0;ni<8;ni++)
            #pragma unroll
            for (int k=0;k<4;k++) d[mi][ni][k]=0.f;

    #pragma unroll
    for (int c = 0; c < 2; c++){
        if (async_path){
            if (c == 0) asm volatile("cp.async.wait_group 1;");
            else        asm volatile("cp.async.wait_group 0;");
            __syncthreads();
        }
        unsigned xA0 = smem_u32(Xc[c]) + (unsigned)(((wr*32 + (lane&15))*XS2 + (lane>>4)*8)*2);
        unsigned xA1 = xA0 + 16*XS2*2;
        unsigned wB  = smem_u32(Wcb[c]) + (unsigned)((((lane&15))*WS2 + wc*64 + (lane>>4)*8)*2);
        #pragma unroll
        for (int ks = 0; ks < 4; ks++){
            unsigned a0[4], a1[4];
            ldmA(a0, xA0 + ks*32);
            ldmA(a1, xA1 + ks*32);
            #pragma unroll
            for (int nt = 0; nt < 4; nt++){
                unsigned bb[4];
                ldmBT(bb, wB + (unsigned)(ks*16*WS2*2) + nt*32);
                mma16816(d[0][2*nt],   a0, bb);
                mma16816(d[0][2*nt+1], a0, bb+2);
                mma16816(d[1][2*nt],   a1, bb);
                mma16816(d[1][2*nt+1], a1, bb+2);
            }
        }
    }

    float gate = 1.f, og = 0.f;
    if (mode & 2){ gate = 1.f/(1.f + expf(-skipPtr[0])); og = 1.f - gate; }
    const int g = lane>>2, t2 = (lane&3)*2;
    float2 bv[8];
    #pragma unroll
    for (int ni=0;ni<8;ni++) bv[ni] = *(const float2*)(B + colBase + wc*64 + ni*8 + t2);

    #pragma unroll
    for (int mi=0;mi<2;mi++){
        int rbase = bRow + wr*32 + mi*16 + g;
        #pragma unroll
        for (int ni=0;ni<8;ni++){
            int c = colBase + wc*64 + ni*8 + t2;
            #pragma unroll
            for (int h=0; h<2; h++){
                int r = rbase + h*8;
                if (r >= N) continue;
                float rx = d[mi][ni][2*h]   + bv[ni].x;
                float ry = d[mi][ni][2*h+1] + bv[ni].y;
                if (mode & 2){
                    __half2 xo = *(const __half2*)(Xold + (size_t)r*128 + c);
                    float2 xf = __half22float2(xo);
                    rx = gate*rx + og*xf.x;
                    ry = gate*ry + og*xf.y;
                }
                if (!(mode & 8)){
                    __half2 hh = __floats2half2_rn(rx, ry);
                    *(__half2*)(Y + (size_t)r*ldy + c) = hh;
                }
                if ((mode & 4) && r < out2N)
                    *(float2*)(out2 + (size_t)r*128 + c) = make_float2(rx, ry);
            }
        }
    }
}

// ---------------- weight prep: fold relation transforms, emit fp16 ----------------
__global__ void prep_weights(const float* __restrict__ k_w, const float* __restrict__ k_b,
                             const float* __restrict__ v_w, const float* __restrict__ v_b,
                             const float* __restrict__ q_w, const float* __restrict__ q_b,
                             const float* __restrict__ a_rel, const float* __restrict__ m_rel,
                             const float* __restrict__ lin_w, const float* __restrict__ a_w)
{
    int fid = blockIdx.x;           // 0..20
    int jc = threadIdx.x;
    int i0 = blockIdx.y * 32;

    if (fid >= 16){
        const float* W = (fid == 16) ? lin_w : a_w + (size_t)(fid-17)*16384;
        __half* D = (fid == 16) ? g_wlinh : g_awh[fid-17];
        for (int i = i0; i < i0+32; i++) D[i*128 + jc] = __float2half(W[i*128 + jc]);
        return;
    }

    int l = fid >> 3, sid = fid & 7;
    bool paper = sid < 5;
    __half* dstW; float* dstB; int stride, col;
    if (paper){ dstW = g_wph[l]; dstB = g_bp[l]; stride = 640; col = sid*128; }
    else      { dstW = g_wah[l]; dstB = g_ba[l]; stride = 384; col = (sid-5)*128; }

    const float *W, *Bi, *R = nullptr;
    switch (sid){
        case 0: W = q_w + (size_t)(l*2+0)*16384; Bi = q_b + (l*2+0)*128; break;
        case 1: W = k_w + (size_t)(l*2+0)*16384; Bi = k_b + (l*2+0)*128; R = a_rel + (size_t)(l*3+1)*4096; break;
        case 2: W = v_w + (size_t)(l*2+0)*16384; Bi = v_b + (l*2+0)*128; R = m_rel + (size_t)(l*3+1)*4096; break;
        case 3: W = k_w + (size_t)(l*2+0)*16384; Bi = k_b + (l*2+0)*128; R = a_rel + (size_t)(l*3+2)*4096; break;
        case 4: W = v_w + (size_t)(l*2+0)*16384; Bi = v_b + (l*2+0)*128; R = m_rel + (size_t)(l*3+2)*4096; break;
        case 5: W = q_w + (size_t)(l*2+1)*16384; Bi = q_b + (l*2+1)*128; break;
        case 6: W = k_w + (size_t)(l*2+1)*16384; Bi = k_b + (l*2+1)*128; R = a_rel + (size_t)(l*3+0)*4096; break;
        default:W = v_w + (size_t)(l*2+1)*16384; Bi = v_b + (l*2+1)*128; R = m_rel + (size_t)(l*3+0)*4096; break;
    }

    if (R == nullptr){
        for (int i = i0; i < i0+32; i++) dstW[i*stride + col + jc] = __float2half(W[i*128 + jc]);
        if (blockIdx.y == 0) dstB[col + jc] = Bi[jc];
        return;
    }
    __shared__ float Rs[4096];
    for (int i = threadIdx.x; i < 4096; i += 128) Rs[i] = R[i];
    __syncthreads();
    int h = jc >> 5, j = jc & 31;
    const float* Rh = Rs + h*1024 + j;
    for (int i = i0; i < i0+32; i++){
        float acc = 0.f;
        #pragma unroll
        for (int dd = 0; dd < 32; dd++) acc += W[i*128 + h*32 + dd] * Rh[dd*32];
        dstW[i*stride + col + jc] = __float2half(acc);
    }
    if (blockIdx.y == 0){
        float accb = 0.f;
        #pragma unroll
        for (int dd = 0; dd < 32; dd++) accb += Bi[h*32 + dd] * Rh[dd*32];
        dstB[col + jc] = accb;
    }
}

// ---------------- merged CSR build ----------------
__global__ void zero_int_kernel(int* __restrict__ p, int n){
    int i = blockIdx.x*blockDim.x + threadIdx.x;
    if (i < n) p[i] = 0;
}
__global__ void hist3_kernel(const int* __restrict__ d0, const int* __restrict__ d1,
                             const int* __restrict__ d2, int* __restrict__ deg){
    int i = blockIdx.x*blockDim.x + threadIdx.x;
    if (i >= 3*NEDGE) return;
    int t = i / NEDGE, e = i - t*NEDGE;
    int d = (t == 0) ? d0[e] : (t == 1) ? d1[e] : d2[e];
    atomicAdd(&deg[t*NP + d], 1);
}
__global__ void partial_kernel(const int* __restrict__ deg, int* __restrict__ part, int n){
    __shared__ int s[256];
    int tid = threadIdx.x;
    int base = blockIdx.x*1024 + tid*4;
    int sum = 0;
    #pragma unroll
    for (int j = 0; j < 4; j++) if (base + j < n) sum += deg[base + j];
    s[tid] = sum; __syncthreads();
    for (int d = 128; d > 0; d >>= 1){
        if (tid < d) s[tid] += s[tid + d];
        __syncthreads();
    }
    if (tid == 0) part[blockIdx.x] = s[0];
}
__global__ void scan_part_kernel(int* __restrict__ part, int nb){
    __shared__ int s[512];
    int tid = threadIdx.x;
    int v = (tid < nb) ? part[tid] : 0;
    s[tid] = v; __syncthreads();
    for (int d = 1; d < 512; d <<= 1){
        int t = (tid >= d) ? s[tid - d] : 0;
        __syncthreads();
        s[tid] += t;
        __syncthreads();
    }
    if (tid < nb) part[tid] = s[tid] - v;
}
__global__ void offsets_kernel(const int* __restrict__ deg, const int* __restrict__ part,
                               int* __restrict__ off, int* __restrict__ cur, int n, int E){
    __shared__ int s[256];
    int tid = threadIdx.x;
    int base = blockIdx.x*1024 + tid*4;
    int v[4];
    #pragma unroll
    for (int j = 0; j < 4; j++) v[j] = (base + j < n) ? deg[base + j] : 0;
    int tsum = v[0]+v[1]+v[2]+v[3];
    s[tid] = tsum; __syncthreads();
    for (int d = 1; d < 256; d <<= 1){
        int t = (tid >= d) ? s[tid - d] : 0;
        __syncthreads();
        s[tid] += t;
        __syncthreads();
    }
    int run = s[tid] - tsum + part[blockIdx.x];
    #pragma unroll
    for (int j = 0; j < 4; j++){
        if (base + j < n){ off[base + j] = run; cur[base + j] = run; }
        run += v[j];
    }
    if (blockIdx.x == 0 && tid == 0) off[n] = E;
}
__global__ void scatter3_kernel(const int* __restrict__ d0, const int* __restrict__ d1,
                                const int* __restrict__ d2, const int* __restrict__ s0,
                                const int* __restrict__ s1, const int* __restrict__ s2,
                                int* __restrict__ cur, int* __restrict__ srcs){
    int i = blockIdx.x*blockDim.x + threadIdx.x;
    if (i >= 3*NEDGE) return;
    int t = i / NEDGE, e = i - t*NEDGE;
    int d  = (t == 0) ? d0[e] : (t == 1) ? d1[e] : d2[e];
    int sv = (t == 0) ? s0[e] : (t == 1) ? s1[e] : s2[e];
    int pos = atomicAdd(&cur[t*NP + d], 1);
    srcs[pos] = sv;
}

// ---------------- single-pass fused attention aggregation (4-wide MLP) ----------------
__device__ __forceinline__ float4 agg_one(int e0, int e1, const int* __restrict__ srcs,
                                          const uint2* __restrict__ buf, int stride4,
                                          int kOff4, int vOff4, float ph, float4 q4, int lane)
{
    float den = 0.f;
    float4 acc = make_float4(0.f,0.f,0.f,0.f);
    for (int base = e0; base < e1; base += 32){
        int m = min(32, e1 - base);
        int myS = (base + lane < e1) ? srcs[base + lane] : 0;
        int j = 0;
        for (; j + 4 <= m; j += 4){
            int s0 = __shfl_sync(0xffffffffu, myS, j);
            int s1 = __shfl_sync(0xffffffffu, myS, j+1);
            int s2 = __shfl_sync(0xffffffffu, myS, j+2);
            int s3 = __shfl_sync(0xffffffffu, myS, j+3);
            const uint2* r0 = buf + (size_t)s0*stride4;
            const uint2* r1 = buf + (size_t)s1*stride4;
            const uint2* r2 = buf + (size_t)s2*stride4;
            const uint2* r3 = buf + (size_t)s3*stride4;
            uint2 k0u = r0[kOff4 + lane], v0u = r0[vOff4 + lane];
            uint2 k1u = r1[kOff4 + lane], v1u = r1[vOff4 + lane];
            uint2 k2u = r2[kOff4 + lane], v2u = r2[vOff4 + lane];
            uint2 k3u = r3[kOff4 + lane], v3u = r3[vOff4 + lane];
            float4 k0 = h4f(k0u), k1 = h4f(k1u), k2 = h4f(k2u), k3 = h4f(k3u);
            float p0 = q4.x*k0.x + q4.y*k0.y + q4.z*k0.z + q4.w*k0.w;
            float p1 = q4.x*k1.x + q4.y*k1.y + q4.z*k1.z + q4.w*k1.w;
            float p2 = q4.x*k2.x + q4.y*k2.y + q4.z*k2.z + q4.w*k2.w;
            float p3 = q4.x*k3.x + q4.y*k3.y + q4.z*k3.z + q4.w*k3.w;
            p0 += __shfl_xor_sync(0xffffffffu, p0, 1);
            p1 += __shfl_xor_sync(0xffffffffu, p1, 1);
            p2 += __shfl_xor_sync(0xffffffffu, p2, 1);
            p3 += __shfl_xor_sync(0xffffffffu, p3, 1);
            p0 += __shfl_xor_sync(0xffffffffu, p0, 2);
            p1 += __shfl_xor_sync(0xffffffffu, p1, 2);
            p2 += __shfl_xor_sync(0xffffffffu, p2, 2);
            p3 += __shfl_xor_sync(0xffffffffu, p3, 2);
            p0 += __shfl_xor_sync(0xffffffffu, p0, 4);
            p1 += __shfl_xor_sync(0xffffffffu, p1, 4);
            p2 += __shfl_xor_sync(0xffffffffu, p2, 4);
            p3 += __shfl_xor_sync(0xffffffffu, p3, 4);
            float e0f = __expf(p0 * ph), e1f = __expf(p1 * ph);
            float e2f = __expf(p2 * ph), e3f = __expf(p3 * ph);
            den += (e0f + e1f) + (e2f + e3f);
            float4 v0 = h4f(v0u), v1 = h4f(v1u), v2 = h4f(v2u), v3 = h4f(v3u);
            acc.x += e0f*v0.x + e1f*v1.x + e2f*v2.x + e3f*v3.x;
            acc.y += e0f*v0.y + e1f*v1.y + e2f*v2.y + e3f*v3.y;
            acc.z += e0f*v0.z + e1f*v1.z + e2f*v2.z + e3f*v3.z;
            acc.w += e0f*v0.w + e1f*v1.w + e2f*v2.w + e3f*v3.w;
        }
        for (; j < m; j++){
            int s = __shfl_sync(0xffffffffu, myS, j);
            const uint2* row = buf + (size_t)s*stride4;
            float4 k4 = h4f(row[kOff4 + lane]);
            float4 v4 = h4f(row[vOff4 + lane]);
            float p = q4.x*k4.x + q4.y*k4.y + q4.z*k4.z + q4.w*k4.w;
            p += __shfl_xor_sync(0xffffffffu, p, 1);
            p += __shfl_xor_sync(0xffffffffu, p, 2);
            p += __shfl_xor_sync(0xffffffffu, p, 4);
            float ex = __expf(p * ph);
            den += ex;
            acc.x += ex*v4.x; acc.y += ex*v4.y;
            acc.z += ex*v4.z; acc.w += ex*v4.w;
        }
    }
    float inv = 1.f/(den + 1e-16f);
    acc.x *= inv; acc.y *= inv; acc.z *= inv; acc.w *= inv;
    return acc;
}

__device__ __forceinline__ void store_h4(__half* dst, float4 v){
    __half2 h0 = __floats2half2_rn(v.x, v.y);
    __half2 h1 = __floats2half2_rn(v.z, v.w);
    uint2 u; u.x = *(unsigned*)&h0; u.y = *(unsigned*)&h1;
    *(uint2*)dst = u;
}

__global__ void aggregate_all(const int* __restrict__ off, const int* __restrict__ srcs,
                              const uint2* __restrict__ actp, const uint2* __restrict__ acta,
                              const float* __restrict__ prel,
                              __half* __restrict__ aggp, __half* __restrict__ agga)
{
    int d = blockIdx.x*8 + (threadIdx.x >> 5);
    int lane = threadIdx.x & 31;
    int h = lane >> 3;
    if (d < NP){
        float4 q4 = h4f(actp[(size_t)d*160 + lane]);
        float ph0 = prel[0*4 + h] * 0.17677669529663687f;
        float ph2 = prel[2*4 + h] * 0.17677669529663687f;
        float4 res = agg_one(off[d], off[d+1], srcs, acta, 96, 32, 64, ph0, q4, lane);
        float4 r2  = agg_one(off[2*NP+d], off[2*NP+d+1], srcs, actp, 160, 96, 128, ph2, q4, lane);
        res.x = gelu_f(0.5f*(res.x + r2.x));
        res.y = gelu_f(0.5f*(res.y + r2.y));
        res.z = gelu_f(0.5f*(res.z + r2.z));
        res.w = gelu_f(0.5f*(res.w + r2.w));
        store_h4(aggp + (size_t)d*128 + lane*4, res);
    } else if (d < NP + NA){
        int da = d - NP;
        float4 q4 = h4f(acta[(size_t)da*96 + lane]);
        float ph1 = prel[1*4 + h] * 0.17677669529663687f;
        float4 res = agg_one(off[NP+da], off[NP+da+1], srcs, actp, 160, 32, 64, ph1, q4, lane);
        res.x = gelu_f(res.x); res.y = gelu_f(res.y);
        res.z = gelu_f(res.z); res.w = gelu_f(res.w);
        store_h4(agga + (size_t)da*128 + lane*4, res);
    }
}

// ---------------- misc ----------------
__global__ void gather_embed_kernel(const float* __restrict__ tab, const int* __restrict__ idx,
                                    __half* __restrict__ out, int n){
    int i = blockIdx.x*blockDim.x + threadIdx.x;
    if (i >= n*32) return;
    int node = i >> 5, c = i & 31;
    int src = idx[node];
    float4 v = ((const float4*)tab)[(size_t)src*32 + c];
    store_h4(out + (size_t)node*128 + c*4, v);
}

// ---------------- launch ----------------
extern "C" void kernel_launch(void* const* d_in, const int* in_sizes, int n_in,
                              void* d_out, int out_size)
{
    const float* x_paper     = (const float*)d_in[0];
    const int*   author_idx  = (const int*)  d_in[1];
    const float* embed_table = (const float*)d_in[2];
    const float* lin_w       = (const float*)d_in[3];
    const float* lin_b       = (const float*)d_in[4];
    const float* k_w         = (const float*)d_in[5];
    const float* k_b         = (const float*)d_in[6];
    const float* q_w         = (const float*)d_in[7];
    const float* q_b         = (const float*)d_in[8];
    const float* v_w         = (const float*)d_in[9];
    const float* v_b         = (const float*)d_in[10];
    const float* a_rel       = (const float*)d_in[11];
    const float* m_rel       = (const float*)d_in[12];
    const float* p_rel       = (const float*)d_in[13];
    const float* skip        = (const float*)d_in[14];
    const float* a_w         = (const float*)d_in[15];
    const float* a_b         = (const float*)d_in[16];
    const int*   w_src       = (const int*)  d_in[17];
    const int*   w_dst       = (const int*)  d_in[18];
    const int*   r_src       = (const int*)  d_in[19];
    const int*   r_dst       = (const int*)  d_in[20];
    const int*   c_src       = (const int*)  d_in[21];
    const int*   c_dst       = (const int*)  d_in[22];
    float* out = (float*)d_out;

    __half *xp,*xa,*actp,*acta,*aggp,*agga,*wlinh;
    __half *wph0,*wah0,*awh0;
    float *bp0,*ba0;
    int *deg,*off,*cur,*srcs,*part;
    cudaGetSymbolAddress((void**)&xp,   g_xp);
    cudaGetSymbolAddress((void**)&xa,   g_xa);
    cudaGetSymbolAddress((void**)&actp, g_actp);
    cudaGetSymbolAddress((void**)&acta, g_acta);
    cudaGetSymbolAddress((void**)&aggp, g_aggp);
    cudaGetSymbolAddress((void**)&agga, g_agga);
    cudaGetSymbolAddress((void**)&wlinh,g_wlinh);
    cudaGetSymbolAddress((void**)&wph0, g_wph);
    cudaGetSymbolAddress((void**)&wah0, g_wah);
    cudaGetSymbolAddress((void**)&awh0, g_awh);
    cudaGetSymbolAddress((void**)&bp0,  g_bp);
    cudaGetSymbolAddress((void**)&ba0,  g_ba);
    cudaGetSymbolAddress((void**)&deg,  g_deg);
    cudaGetSymbolAddress((void**)&off,  g_off);
    cudaGetSymbolAddress((void**)&cur,  g_cur);
    cudaGetSymbolAddress((void**)&srcs, g_srcs);
    cudaGetSymbolAddress((void**)&part, g_part);

    cudaFuncSetAttribute(gemm_mma, cudaFuncAttributeMaxDynamicSharedMemorySize, SMEM_BYTES);

    // side streams + events, created once (CPU-side resources only; graph identical per call)
    static cudaStream_t sB = nullptr, sC = nullptr;
    static cudaEvent_t ev0, evPrep, evCSR, evA0, evAgg0, evA1, evAgg1, evA2;
    if (!sB){
        cudaStreamCreateWithFlags(&sB, cudaStreamNonBlocking);
        cudaStreamCreateWithFlags(&sC, cudaStreamNonBlocking);
        cudaEventCreateWithFlags(&ev0,   cudaEventDisableTiming);
        cudaEventCreateWithFlags(&evPrep,cudaEventDisableTiming);
        cudaEventCreateWithFlags(&evCSR, cudaEventDisableTiming);
        cudaEventCreateWithFlags(&evA0,  cudaEventDisableTiming);
        cudaEventCreateWithFlags(&evAgg0,cudaEventDisableTiming);
        cudaEventCreateWithFlags(&evA1,  cudaEventDisableTiming);
        cudaEventCreateWithFlags(&evAgg1,cudaEventDisableTiming);
        cudaEventCreateWithFlags(&evA2,  cudaEventDisableTiming);
    }

    const int SMB = SMEM_BYTES;
    const int GP = (NP+127)/128, GA = (NA+127)/128;

    cudaEventRecord(ev0, 0);

    // ---- stream B: CSR build (independent until aggregate l0) ----
    cudaStreamWaitEvent(sB, ev0, 0);
    {
        int n = 3*NP;
        int nb = (n + 1023)/1024;
        zero_int_kernel<<<(n+255)/256,256,0,sB>>>(deg, n);
        hist3_kernel<<<(3*NEDGE+255)/256,256,0,sB>>>(w_dst, r_dst, c_dst, deg);
        partial_kernel<<<nb,256,0,sB>>>(deg, part, n);
        scan_part_kernel<<<1,512,0,sB>>>(part, nb);
        offsets_kernel<<<nb,256,0,sB>>>(deg, part, off, cur, n, 3*NEDGE);
        scatter3_kernel<<<(3*NEDGE+255)/256,256,0,sB>>>(w_dst, r_dst, c_dst, w_src, r_src, c_src, cur, srcs);
    }
    cudaEventRecord(evCSR, sB);

    // ---- stream C: author embed gather (independent of prep) ----
    cudaStreamWaitEvent(sC, ev0, 0);
    gather_embed_kernel<<<(NA*32+255)/256,256,0,sC>>>(embed_table, author_idx, xa, NA);

    // ---- main: weight prep ----
    prep_weights<<<dim3(21,4),128>>>(k_w, k_b, v_w, v_b, q_w, q_b, a_rel, m_rel, lin_w, a_w);
    cudaEventRecord(evPrep, 0);

    // stream C: author QKV l=0 (needs xa + wah)
    cudaStreamWaitEvent(sC, evPrep, 0);
    gemm_mma<<<dim3(GA,3),256,SMB,sC>>>(xa, wah0 + (size_t)0*128*384, 384, ba0 + 0*384,
                                        acta, 384, nullptr, nullptr, nullptr, 0, NA, 0);
    cudaEventRecord(evA0, sC);

    // main: input projection + paper QKV l=0
    gemm_mma<<<dim3(GP,1),256,SMB>>>(x_paper, wlinh, 128, lin_b, xp, 128,
                                     nullptr, nullptr, nullptr, 0, NP, 1);
    gemm_mma<<<dim3(GP,5),256,SMB>>>(xp, wph0, 640, bp0,
                                     actp, 640, nullptr, nullptr, nullptr, 0, NP, 0);

    // aggregate l=0 (needs CSR + actp + acta)
    cudaStreamWaitEvent(0, evCSR, 0);
    cudaStreamWaitEvent(0, evA0, 0);
    aggregate_all<<<(NP+NA+7)/8,256>>>(off, srcs, (const uint2*)actp, (const uint2*)acta,
                                       p_rel + 0, aggp, agga);
    cudaEventRecord(evAgg0, 0);

    // stream C: author update l=0 + author QKV l=1
    cudaStreamWaitEvent(sC, evAgg0, 0);
    gemm_mma<<<dim3(GA,1),256,SMB,sC>>>(agga, awh0 + (size_t)1*16384, 128, a_b + 1*128,
                                        xa, 128, xa, skip + 1,
                                        nullptr, 0, NA, 2);
    gemm_mma<<<dim3(GA,3),256,SMB,sC>>>(xa, wah0 + (size_t)1*128*384, 384, ba0 + 1*384,
                                        acta, 384, nullptr, nullptr, nullptr, 0, NA, 0);
    cudaEventRecord(evA1, sC);

    // main: paper update l=0 + paper QKV l=1
    gemm_mma<<<dim3(GP,1),256,SMB>>>(aggp, awh0 + (size_t)0*16384, 128, a_b + 0*128,
                                     xp, 128, xp, skip + 0,
                                     nullptr, 0, NP, 2);
    gemm_mma<<<dim3(GP,5),256,SMB>>>(xp, wph0 + (size_t)1*128*640, 640, bp0 + 1*640,
                                     actp, 640, nullptr, nullptr, nullptr, 0, NP, 0);

    // aggregate l=1
    cudaStreamWaitEvent(0, evA1, 0);
    aggregate_all<<<(NP+NA+7)/8,256>>>(off, srcs, (const uint2*)actp, (const uint2*)acta,
                                       p_rel + 12, aggp, agga);
    cudaEventRecord(evAgg1, 0);

    // stream C: author final update (fp32 out rows)
    cudaStreamWaitEvent(sC, evAgg1, 0);
    gemm_mma<<<dim3(GA,1),256,SMB,sC>>>(agga, awh0 + (size_t)3*16384, 128, a_b + 3*128,
                                        xa, 128, xa, skip + 3,
                                        out + (size_t)50000*128, 25000, NA, 2|4|8);
    cudaEventRecord(evA2, sC);

    // main: paper final update
    gemm_mma<<<dim3(GP,1),256,SMB>>>(aggp, awh0 + (size_t)2*16384, 128, a_b + 2*128,
                                     xp, 128, xp, skip + 2,
                                     out, 50000, NP, 2|4|8);
    cudaStreamWaitEvent(0, evA2, 0);
}